// round 3
// baseline (speedup 1.0000x reference)
#include <cuda_runtime.h>
#include <math.h>
#include <stddef.h>

#define B_TOT 4096
#define T_STEPS 200
#define DS 32
#define DA 8
#define HH 128
#define TH 384   // 3*H
#define KIN 40   // Ds+Da

// Scratch (allocation-free rule: __device__ globals)
__device__ float g_h[B_TOT * HH];    // hidden state, fp32
__device__ float g_gh[B_TOT * TH];   // h @ Whh^T + bhh, fp32

__device__ __forceinline__ float sigf(float x) { return 1.0f / (1.0f + expf(-x)); }

// ---------------------------------------------------------------------------
// init: zero hidden state
// ---------------------------------------------------------------------------
__global__ void init_h_kernel() {
    int i = blockIdx.x * blockDim.x + threadIdx.x;
    if (i < B_TOT * HH) g_h[i] = 0.0f;
}

// ---------------------------------------------------------------------------
// Flow kernel: one flow block layer.
//   inp = [h, t]  (129)
//   r = 0.8*sig(inp@Wr+br); z = 0.4*sig(inp@Wz+bz)
//   u = tanh([r*h, t]@Wh + bh); phi = tanh(tw * t)
//   h' = h + phi*z*(u-h)
// 128 CTAs x 32 rows. 256 threads: n = tid&127 (output col), half = tid>>7
// (16 rows each). Weights (3 x 129x128 fp32 = 198KB) staged in smem.
// ---------------------------------------------------------------------------
#define FLOW_SMEM_FLOATS (3*16512 + 4*128 + 32*128 + 32)

__global__ void __launch_bounds__(256, 1)
flow_kernel(const float* __restrict__ Wr, const float* __restrict__ br,
            const float* __restrict__ Wz, const float* __restrict__ bz,
            const float* __restrict__ Wh, const float* __restrict__ bh,
            const float* __restrict__ tw, const float* __restrict__ t_all,
            float* __restrict__ hids, int t_idx)
{
    extern __shared__ float sm[];
    float* sWr = sm;                  // 129*128
    float* sWz = sWr + 16512;
    float* sWh = sWz + 16512;
    float* sbr = sWh + 16512;         // 128
    float* sbz = sbr + 128;
    float* sbh = sbz + 128;
    float* stw = sbh + 128;
    float* sIn = stw + 128;           // 32*128
    float* sT  = sIn + 4096;          // 32

    const int tid  = threadIdx.x;
    const int row0 = blockIdx.x * 32;

    // stage weights (coalesced float4)
    {
        const float4* gr = (const float4*)Wr;
        const float4* gz = (const float4*)Wz;
        const float4* gh = (const float4*)Wh;
        float4* s1 = (float4*)sWr; float4* s2 = (float4*)sWz; float4* s3 = (float4*)sWh;
        for (int i = tid; i < 4128; i += 256) { s1[i] = gr[i]; s2[i] = gz[i]; s3[i] = gh[i]; }
    }
    if (tid < 128) { sbr[tid] = br[tid]; sbz[tid] = bz[tid]; sbh[tid] = bh[tid]; stw[tid] = tw[tid]; }
    {
        const float4* gH = (const float4*)(g_h + (size_t)row0 * HH);
        float4* sI = (float4*)sIn;
        for (int i = tid; i < 1024; i += 256) sI[i] = gH[i];
    }
    if (tid < 32) sT[tid] = t_all[(size_t)(row0 + tid) * T_STEPS + t_idx];
    __syncthreads();

    const int n  = tid & 127;
    const int m0 = (tid >> 7) * 16;

    float hc[16], ar[16], az[16];
#pragma unroll
    for (int m = 0; m < 16; m++) {
        hc[m] = sIn[(m0 + m) * HH + n];
        ar[m] = 0.0f; az[m] = 0.0f;
    }

    // r,z matvecs over k=0..127 (vectorized input reads, weights per-column)
    for (int k = 0; k < 128; k += 4) {
        const float wr0 = sWr[(k+0)*HH + n], wr1 = sWr[(k+1)*HH + n];
        const float wr2 = sWr[(k+2)*HH + n], wr3 = sWr[(k+3)*HH + n];
        const float wz0 = sWz[(k+0)*HH + n], wz1 = sWz[(k+1)*HH + n];
        const float wz2 = sWz[(k+2)*HH + n], wz3 = sWz[(k+3)*HH + n];
#pragma unroll
        for (int m = 0; m < 16; m++) {
            const float4 x = *(const float4*)&sIn[(m0 + m) * HH + k];
            ar[m] = fmaf(x.x, wr0, fmaf(x.y, wr1, fmaf(x.z, wr2, fmaf(x.w, wr3, ar[m]))));
            az[m] = fmaf(x.x, wz0, fmaf(x.y, wz1, fmaf(x.z, wz2, fmaf(x.w, wz3, az[m]))));
        }
    }
    // k = 128 (time feature row)
    {
        const float wrt = sWr[128*HH + n], wzt = sWz[128*HH + n];
#pragma unroll
        for (int m = 0; m < 16; m++) {
            const float tv = sT[m0 + m];
            ar[m] = fmaf(tv, wrt, ar[m]);
            az[m] = fmaf(tv, wzt, az[m]);
        }
    }
    float rr[16], zz[16];
    {
        const float bnr = sbr[n], bnz = sbz[n];
#pragma unroll
        for (int m = 0; m < 16; m++) {
            rr[m] = 0.8f * sigf(ar[m] + bnr);   // BETA = 4/5
            zz[m] = 0.4f * sigf(az[m] + bnz);   // ALPHA = 2/5
        }
    }
    __syncthreads();                  // everyone done reading h tile
#pragma unroll
    for (int m = 0; m < 16; m++) sIn[(m0 + m) * HH + n] = rr[m] * hc[m];
    __syncthreads();                  // r*h tile visible

    float au[16];
#pragma unroll
    for (int m = 0; m < 16; m++) au[m] = 0.0f;
    for (int k = 0; k < 128; k += 4) {
        const float wh0 = sWh[(k+0)*HH + n], wh1 = sWh[(k+1)*HH + n];
        const float wh2 = sWh[(k+2)*HH + n], wh3 = sWh[(k+3)*HH + n];
#pragma unroll
        for (int m = 0; m < 16; m++) {
            const float4 x = *(const float4*)&sIn[(m0 + m) * HH + k];
            au[m] = fmaf(x.x, wh0, fmaf(x.y, wh1, fmaf(x.z, wh2, fmaf(x.w, wh3, au[m]))));
        }
    }
    {
        const float wht = sWh[128*HH + n];
        const float bnh = sbh[n];
        const float twn = stw[n];
#pragma unroll
        for (int m = 0; m < 16; m++) {
            const float tv  = sT[m0 + m];
            const float u   = tanhf(fmaf(tv, wht, au[m]) + bnh);
            const float phi = tanhf(twn * tv);
            const float hn  = hc[m] + phi * zz[m] * (u - hc[m]);
            const int row   = row0 + m0 + m;
            g_h[(size_t)row * HH + n] = hn;
            if (hids) hids[((size_t)row * T_STEPS + t_idx) * HH + n] = hn;
        }
    }
}

// ---------------------------------------------------------------------------
// gh kernel: g_gh = h @ Whh^T + bhh   (Whh: [384,128] fp32, 192KB in smem,
// stored transposed with pad-385 to keep both the transpose-write and the
// per-column compute read conflict-free). 128 CTAs x 32 rows, 384 threads.
// ---------------------------------------------------------------------------
#define GH_SMEM_FLOATS (128*385 + 384 + 32*128)

__global__ void __launch_bounds__(384, 1)
gh_kernel(const float* __restrict__ Whh, const float* __restrict__ bhh)
{
    extern __shared__ float sm[];
    float* sW  = sm;            // [k*385 + j], 128x384 padded
    float* sb  = sW + 128*385;  // 384
    float* sIn = sb + 384;      // 32*128

    const int tid  = threadIdx.x;
    const int row0 = blockIdx.x * 32;

    for (int idx = tid; idx < TH * HH; idx += 384) {
        const int j = idx >> 7;       // 0..383
        const int k = idx & 127;      // 0..127
        sW[k * 385 + j] = Whh[idx];
    }
    sb[tid] = bhh[tid];
    {
        const float4* gH = (const float4*)(g_h + (size_t)row0 * HH);
        float4* sI = (float4*)sIn;
        for (int i = tid; i < 1024; i += 384) sI[i] = gH[i];
    }
    __syncthreads();

    float acc[32];
#pragma unroll
    for (int m = 0; m < 32; m++) acc[m] = 0.0f;

    for (int k = 0; k < 128; k += 4) {
        const float w0 = sW[(k+0)*385 + tid], w1 = sW[(k+1)*385 + tid];
        const float w2 = sW[(k+2)*385 + tid], w3 = sW[(k+3)*385 + tid];
#pragma unroll
        for (int m = 0; m < 32; m++) {
            const float4 x = *(const float4*)&sIn[m * HH + k];
            acc[m] = fmaf(x.x, w0, fmaf(x.y, w1, fmaf(x.z, w2, fmaf(x.w, w3, acc[m]))));
        }
    }
    const float b = sb[tid];
#pragma unroll
    for (int m = 0; m < 32; m++)
        g_gh[(size_t)(row0 + m) * TH + tid] = acc[m] + b;
}

// ---------------------------------------------------------------------------
// GRU + decoder kernel:
//   gi = x@Wih^T + bih ; r,z = sig ; n = tanh(gi_n + r*gh_n)
//   h' = (1-z)n + z*h ; o = h'@decW^T + dec_b
// 128 CTAs x 32 rows, 128 threads (thread n = hidden unit; 3 gates each).
// ---------------------------------------------------------------------------
#define GRU_SMEM_FLOATS (40*385 + 128*33 + 32*384 + 32*40 + 32*128 + 32*128 + 384 + 32)

__global__ void __launch_bounds__(128, 1)
gru_kernel(const float* __restrict__ s_in, const float* __restrict__ a_in,
           const float* __restrict__ Wih,  const float* __restrict__ bih,
           const float* __restrict__ decW, const float* __restrict__ decb,
           float* __restrict__ outs, int t_idx)
{
    extern __shared__ float sm[];
    float* sWih = sm;             // [k*385 + j], 40x384 padded
    float* sDec = sWih + 40*385;  // [k*33 + d], 128x32 padded
    float* sGh  = sDec + 128*33;  // 32*384
    float* sX   = sGh + 32*384;   // 32*40
    float* sHp  = sX + 32*40;     // 32*128  (h after flow)
    float* sHn  = sHp + 32*128;   // 32*128  (h_new)
    float* sBih = sHn + 32*128;   // 384
    float* sDb  = sBih + 384;     // 32

    const int tid  = threadIdx.x;
    const int row0 = blockIdx.x * 32;

    for (int idx = tid; idx < TH * KIN; idx += 128) {
        const int j = idx / KIN;
        const int k = idx - j * KIN;
        sWih[k * 385 + j] = Wih[idx];
    }
    for (int idx = tid; idx < DS * HH; idx += 128) {
        const int d = idx >> 7;
        const int k = idx & 127;
        sDec[k * 33 + d] = decW[idx];
    }
    {
        const float4* gG = (const float4*)(g_gh + (size_t)row0 * TH);
        float4* sG = (float4*)sGh;
        for (int i = tid; i < (32 * TH) / 4; i += 128) sG[i] = gG[i];
        const float4* gH = (const float4*)(g_h + (size_t)row0 * HH);
        float4* sH = (float4*)sHp;
        for (int i = tid; i < 1024; i += 128) sH[i] = gH[i];
    }
    for (int idx = tid; idx < 32 * KIN; idx += 128) {
        const int m = idx / KIN;
        const int c = idx - m * KIN;
        const size_t row = row0 + m;
        sX[idx] = (c < DS) ? s_in[(row * T_STEPS + t_idx) * DS + c]
                           : a_in[(row * T_STEPS + t_idx) * DA + (c - DS)];
    }
    for (int idx = tid; idx < TH; idx += 128) sBih[idx] = bih[idx];
    if (tid < 32) sDb[tid] = decb[tid];
    __syncthreads();

    const int n = tid;
    const float b_r = sBih[n], b_z = sBih[128 + n], b_n = sBih[256 + n];

    // process rows in subtiles of 8 (weights hoisted over rows)
    for (int ms = 0; ms < 4; ms++) {
        float gr[8], gz[8], gn[8];
#pragma unroll
        for (int mm = 0; mm < 8; mm++) { gr[mm] = b_r; gz[mm] = b_z; gn[mm] = b_n; }
        for (int k = 0; k < KIN; k++) {
            const float wr = sWih[k*385 + n];
            const float wz = sWih[k*385 + 128 + n];
            const float wn = sWih[k*385 + 256 + n];
#pragma unroll
            for (int mm = 0; mm < 8; mm++) {
                const float x = sX[(ms*8 + mm) * KIN + k];
                gr[mm] = fmaf(x, wr, gr[mm]);
                gz[mm] = fmaf(x, wz, gz[mm]);
                gn[mm] = fmaf(x, wn, gn[mm]);
            }
        }
#pragma unroll
        for (int mm = 0; mm < 8; mm++) {
            const int m   = ms*8 + mm;
            const float ghr = sGh[m*TH + n];
            const float ghz = sGh[m*TH + 128 + n];
            const float ghn = sGh[m*TH + 256 + n];
            const float h   = sHp[m*HH + n];
            const float r   = sigf(gr[mm] + ghr);
            const float z   = sigf(gz[mm] + ghz);
            const float nn  = tanhf(fmaf(r, ghn, gn[mm]));
            const float hn  = (1.0f - z) * nn + z * h;
            g_h[(size_t)(row0 + m) * HH + n] = hn;
            sHn[m*HH + n] = hn;
        }
    }
    __syncthreads();

    // decoder: threads = 32 cols x 4 row-groups of 8
    const int d  = tid & 31;
    const int mg = tid >> 5;
#pragma unroll
    for (int mm = 0; mm < 8; mm++) {
        const int m = mg * 8 + mm;
        float acc = sDb[d];
        for (int k = 0; k < 128; k += 4) {
            const float4 hv = *(const float4*)&sHn[m * HH + k];
            acc = fmaf(hv.x, sDec[(k+0)*33 + d], acc);
            acc = fmaf(hv.y, sDec[(k+1)*33 + d], acc);
            acc = fmaf(hv.z, sDec[(k+2)*33 + d], acc);
            acc = fmaf(hv.w, sDec[(k+3)*33 + d], acc);
        }
        const size_t row = row0 + m;
        outs[(row * T_STEPS + t_idx) * DS + d] = acc;
    }
}

// ---------------------------------------------------------------------------
// launch
// ---------------------------------------------------------------------------
extern "C" void kernel_launch(void* const* d_in, const int* in_sizes, int n_in,
                              void* d_out, int out_size)
{
    const float* s    = (const float*)d_in[0];
    const float* a    = (const float*)d_in[1];
    const float* t    = (const float*)d_in[2];
    const float* fWr  = (const float*)d_in[3];
    const float* fbr  = (const float*)d_in[4];
    const float* fWz  = (const float*)d_in[5];
    const float* fbz  = (const float*)d_in[6];
    const float* fWh  = (const float*)d_in[7];
    const float* fbh  = (const float*)d_in[8];
    const float* ftw  = (const float*)d_in[9];
    const float* Wih  = (const float*)d_in[10];
    const float* Whh  = (const float*)d_in[11];
    const float* bih  = (const float*)d_in[12];
    const float* bhh  = (const float*)d_in[13];
    const float* decW = (const float*)d_in[14];
    const float* decb = (const float*)d_in[15];

    float* outs = (float*)d_out;
    float* hids = outs + (size_t)B_TOT * T_STEPS * DS;

    const int FLOW_SMEM = FLOW_SMEM_FLOATS * 4;
    const int GH_SMEM   = GH_SMEM_FLOATS * 4;
    const int GRU_SMEM  = GRU_SMEM_FLOATS * 4;

    cudaFuncSetAttribute(flow_kernel, cudaFuncAttributeMaxDynamicSharedMemorySize, FLOW_SMEM);
    cudaFuncSetAttribute(gh_kernel,   cudaFuncAttributeMaxDynamicSharedMemorySize, GH_SMEM);
    cudaFuncSetAttribute(gru_kernel,  cudaFuncAttributeMaxDynamicSharedMemorySize, GRU_SMEM);

    init_h_kernel<<<(B_TOT * HH + 255) / 256, 256>>>();

    const int WSTRIDE = 129 * HH;  // per-layer flow weight stride
    for (int ti = 0; ti < T_STEPS; ti++) {
        flow_kernel<<<128, 256, FLOW_SMEM>>>(fWr, fbr, fWz, fbz, fWh, fbh, ftw,
                                             t, (float*)0, ti);
        flow_kernel<<<128, 256, FLOW_SMEM>>>(fWr + WSTRIDE, fbr + HH,
                                             fWz + WSTRIDE, fbz + HH,
                                             fWh + WSTRIDE, fbh + HH,
                                             ftw + HH, t, hids, ti);
        gh_kernel<<<128, 384, GH_SMEM>>>(Whh, bhh);
        gru_kernel<<<128, 128, GRU_SMEM>>>(s, a, Wih, bih, decW, decb, outs, ti);
    }
}

// round 4
// speedup vs baseline: 1.8334x; 1.8334x over previous
#include <cuda_runtime.h>
#include <stddef.h>

#define T_STEPS 200
#define DS 32
#define DA 8
#define HH 128
#define NTHR 256

typedef unsigned long long u64;

// ---- smem layout (float offsets) ----
#define SLOT    16896            // staging slot size (floats)
#define OFF_S0  0
#define OFF_S1  16896
#define OFF_DEC 33792            // decT [d][k] stride 132  (32*132)
#define OFF_HT  38016            // h    [pair][k] float2, stride 264 fl (16*264)
#define OFF_RH  42240            // r*h  same layout
#define OFF_XT  46464            // gru x [pair][k<40] float2, stride 88 (16*88)
#define OFF_FB  47872            // flow biases [l*512 + part*128 + n], parts r,z,h,tw
#define OFF_BIH 48896            // 384
#define OFF_BHH 49280            // 384
#define OFF_DB  49664            // 32
#define OFF_TV  49696            // 32
#define SMEM_FL 49728            // *4 = 198912 bytes

// ---- packed helpers ----
__device__ __forceinline__ u64 pk2(float lo, float hi) {
    u64 r; asm("mov.b64 %0,{%1,%2};" : "=l"(r) : "f"(lo), "f"(hi)); return r;
}
__device__ __forceinline__ void up2(u64 v, float& lo, float& hi) {
    asm("mov.b64 {%0,%1},%2;" : "=f"(lo), "=f"(hi) : "l"(v));
}
__device__ __forceinline__ u64 fma2(u64 a, u64 b, u64 c) {
    u64 d; asm("fma.rn.f32x2 %0,%1,%2,%3;" : "=l"(d) : "l"(a), "l"(b), "l"(c)); return d;
}
__device__ __forceinline__ u64 mul2(u64 a, u64 b) {
    u64 d; asm("mul.rn.f32x2 %0,%1,%2;" : "=l"(d) : "l"(a), "l"(b)); return d;
}
__device__ __forceinline__ u64 add2(u64 a, u64 b) {
    u64 d; asm("add.rn.f32x2 %0,%1,%2;" : "=l"(d) : "l"(a), "l"(b)); return d;
}
__device__ __forceinline__ void lds2x64(u64& a, u64& b, unsigned addr) {
    asm volatile("ld.shared.v2.b64 {%0,%1},[%2];" : "=l"(a), "=l"(b) : "r"(addr));
}
__device__ __forceinline__ float tanha(float x) {
    float y; asm("tanh.approx.f32 %0,%1;" : "=f"(y) : "f"(x)); return y;
}
__device__ __forceinline__ float siga(float x) { return fmaf(0.5f, tanha(0.5f * x), 0.5f); }
__device__ __forceinline__ u64 tanh2(u64 v) { float a, b; up2(v, a, b); return pk2(tanha(a), tanha(b)); }
__device__ __forceinline__ u64 sub2(u64 a, u64 b) { float x,y,p,q; up2(a,x,y); up2(b,p,q); return pk2(x-p, y-q); }

__device__ __forceinline__ void cpa16(float* dst, const float* src) {
    unsigned d = (unsigned)__cvta_generic_to_shared(dst);
    asm volatile("cp.async.cg.shared.global [%0], [%1], 16;" :: "r"(d), "l"(src));
}
#define CP_COMMIT() asm volatile("cp.async.commit_group;" ::: "memory")
#define CP_WAIT0()  asm volatile("cp.async.wait_group 0;" ::: "memory")

// stage matrix for phase ph into slot ph&1
__device__ __forceinline__ void stage_matrix(int ph, float* sm, int tid,
    const float* fWr, const float* fWz, const float* fWh,
    const float* Whh, const float* Wih)
{
    float* dst = sm + (ph & 1) * SLOT;
    if (ph < 6) {
        const int l = ph / 3, w = ph % 3;
        const float* src = (w == 0 ? fWr : (w == 1 ? fWz : fWh)) + (size_t)l * 129 * 128;
        for (int i = tid; i < 4128; i += NTHR) cpa16(dst + i * 4, src + i * 4);
    } else if (ph < 9) {
        const float* src = Whh + (size_t)(ph - 6) * 128 * 128;
        for (int i = tid; i < 4096; i += NTHR) {
            int r = i >> 5, c = i & 31;
            cpa16(dst + r * 132 + c * 4, src + r * 128 + c * 4);
        }
    } else {
        for (int i = tid; i < 3840; i += NTHR) {
            int r = i / 10, c = i - r * 10;
            cpa16(dst + r * 44 + c * 4, Wih + r * 40 + c * 4);
        }
    }
}

// matvec pass: weights [k][n] (flow layout), x packed [pair][k] stride 1056B
__device__ __forceinline__ void pass_kn(const float* sW, unsigned xaddr, int n, u64 acc[8])
{
    for (int k = 0; k < 128; k += 2) {
        const float w0 = sW[k * 128 + n];
        const float w1 = sW[k * 128 + 128 + n];
        const u64 w02 = pk2(w0, w0), w12 = pk2(w1, w1);
#pragma unroll
        for (int p = 0; p < 8; p++) {
            u64 x0, x1;
            lds2x64(x0, x1, xaddr + p * 1056 + k * 8);
            acc[p] = fma2(x0, w02, acc[p]);
            acc[p] = fma2(x1, w12, acc[p]);
        }
    }
}

// matvec pass: weights [n][k] stride 132 (gh gate layout), x = hT
__device__ __forceinline__ void pass_nk(const float* sW, unsigned xaddr, int n, u64 acc[8])
{
    for (int k = 0; k < 128; k += 4) {
        const float4 w = *(const float4*)&sW[n * 132 + k];
        const u64 wa = pk2(w.x, w.x), wb = pk2(w.y, w.y);
        const u64 wc = pk2(w.z, w.z), wd = pk2(w.w, w.w);
#pragma unroll
        for (int p = 0; p < 8; p++) {
            u64 x0, x1, x2, x3;
            lds2x64(x0, x1, xaddr + p * 1056 + k * 8);
            lds2x64(x2, x3, xaddr + p * 1056 + k * 8 + 16);
            acc[p] = fma2(x0, wa, acc[p]);
            acc[p] = fma2(x1, wb, acc[p]);
            acc[p] = fma2(x2, wc, acc[p]);
            acc[p] = fma2(x3, wd, acc[p]);
        }
    }
}

__global__ void __launch_bounds__(NTHR, 1)
odernn_persistent(const float* __restrict__ s,   const float* __restrict__ a,
                  const float* __restrict__ t,
                  const float* __restrict__ fWr, const float* __restrict__ fbr,
                  const float* __restrict__ fWz, const float* __restrict__ fbz,
                  const float* __restrict__ fWh, const float* __restrict__ fbh,
                  const float* __restrict__ ftw,
                  const float* __restrict__ Wih, const float* __restrict__ Whh,
                  const float* __restrict__ bih, const float* __restrict__ bhh,
                  const float* __restrict__ decW, const float* __restrict__ decb,
                  float* __restrict__ outs, float* __restrict__ hids)
{
    extern __shared__ float sm[];
    const int tid  = threadIdx.x;
    const int row0 = blockIdx.x * 32;
    const unsigned sbase = (unsigned)__cvta_generic_to_shared(sm);

    const int n  = tid & 127;          // output column
    const int p0 = (tid >> 7) * 8;     // first row-pair (8 pairs per thread)

    const unsigned htaddr = sbase + (OFF_HT + p0 * 264) * 4;
    const unsigned rhaddr = sbase + (OFF_RH + p0 * 264) * 4;
    const unsigned xtaddr = sbase + (OFF_XT + p0 * 88) * 4;

    // ---- one-time init ----
    for (int i = tid; i < 16 * 264; i += NTHR) sm[OFF_HT + i] = 0.0f;
    if (tid < 128) {
#pragma unroll
        for (int l = 0; l < 2; l++) {
            sm[OFF_FB + l * 512 +   0 + tid] = fbr[l * HH + tid];
            sm[OFF_FB + l * 512 + 128 + tid] = fbz[l * HH + tid];
            sm[OFF_FB + l * 512 + 256 + tid] = fbh[l * HH + tid];
            sm[OFF_FB + l * 512 + 384 + tid] = ftw[l * HH + tid];
        }
    }
    for (int i = tid; i < 384; i += NTHR) { sm[OFF_BIH + i] = bih[i]; sm[OFF_BHH + i] = bhh[i]; }
    if (tid < 32) sm[OFF_DB + tid] = decb[tid];
    // stage decoder weights [d][k] stride 132 + first matrix (Wr0 -> slot0)
    for (int i = tid; i < 1024; i += NTHR) {
        int r = i >> 5, c = i & 31;
        cpa16(sm + OFF_DEC + r * 132 + c * 4, decW + r * 128 + c * 4);
    }
    stage_matrix(0, sm, tid, fWr, fWz, fWh, Whh, Wih);
    CP_COMMIT();

    for (int ti = 0; ti < T_STEPS; ti++) {
        // per-step global loads (visible after phase-0 boundary sync)
        if (tid < 32) sm[OFF_TV + tid] = t[(size_t)(row0 + tid) * T_STEPS + ti];
        for (int i = tid; i < 32 * 40; i += NTHR) {
            const int m = i / 40, c = i - m * 40;
            const size_t row = row0 + m;
            const float v = (c < DS) ? s[(row * T_STEPS + ti) * DS + c]
                                     : a[(row * T_STEPS + ti) * DA + (c - DS)];
            sm[OFF_XT + (m >> 1) * 88 + 2 * c + (m & 1)] = v;
        }

        u64 zz2[8];   // z-gate (flow) kept across passes
        u64 tvp[8];

        // =================== flow layers ===================
#pragma unroll 1
        for (int l = 0; l < 2; l++) {
            const int phb = l * 3;
            const float* bias = sm + OFF_FB + l * 512;

            // ---- pass r ----
            CP_WAIT0(); __syncthreads();
            stage_matrix(phb + 1, sm, tid, fWr, fWz, fWh, Whh, Wih); CP_COMMIT();
            {
                const float* sW = sm + (phb & 1) * SLOT;
#pragma unroll
                for (int p = 0; p < 8; p++)
                    tvp[p] = pk2(sm[OFF_TV + 2 * (p0 + p)], sm[OFF_TV + 2 * (p0 + p) + 1]);
                u64 acc[8];
#pragma unroll
                for (int p = 0; p < 8; p++) acc[p] = 0ULL;
                pass_kn(sW, htaddr, n, acc);
                const float w128 = sW[16384 + n];
                const u64 w1282 = pk2(w128, w128);
                const float br_n = bias[n];
#pragma unroll
                for (int p = 0; p < 8; p++) {
                    acc[p] = fma2(tvp[p], w1282, acc[p]);
                    float x, y; up2(acc[p], x, y);
                    const u64 rr2 = pk2(0.8f * siga(x + br_n), 0.8f * siga(y + br_n));
                    const u64 h2 = *(const u64*)&sm[OFF_HT + (p0 + p) * 264 + 2 * n];
                    *(u64*)&sm[OFF_RH + (p0 + p) * 264 + 2 * n] = mul2(rr2, h2);
                }
            }

            // ---- pass z ----
            CP_WAIT0(); __syncthreads();
            stage_matrix(phb + 2, sm, tid, fWr, fWz, fWh, Whh, Wih); CP_COMMIT();
            {
                const float* sW = sm + ((phb + 1) & 1) * SLOT;
                u64 acc[8];
#pragma unroll
                for (int p = 0; p < 8; p++) acc[p] = 0ULL;
                pass_kn(sW, htaddr, n, acc);
                const float w128 = sW[16384 + n];
                const u64 w1282 = pk2(w128, w128);
                const float bz_n = bias[128 + n];
#pragma unroll
                for (int p = 0; p < 8; p++) {
                    acc[p] = fma2(tvp[p], w1282, acc[p]);
                    float x, y; up2(acc[p], x, y);
                    zz2[p] = pk2(0.4f * siga(x + bz_n), 0.4f * siga(y + bz_n));
                }
            }

            // ---- pass u + combine ----
            CP_WAIT0(); __syncthreads();
            {   // next phase: flow(l=1) starts at 3, or ghr at 6
                stage_matrix(phb + 3, sm, tid, fWr, fWz, fWh, Whh, Wih); CP_COMMIT();
                const float* sW = sm + ((phb + 2) & 1) * SLOT;
                u64 acc[8];
#pragma unroll
                for (int p = 0; p < 8; p++) acc[p] = 0ULL;
                pass_kn(sW, rhaddr, n, acc);
                const float w128 = sW[16384 + n];
                const u64 w1282 = pk2(w128, w128);
                const float bh_n = bias[256 + n];
                const float tw_n = bias[384 + n];
                const u64 bh2 = pk2(bh_n, bh_n);
                const u64 tw2 = pk2(tw_n, tw_n);
#pragma unroll
                for (int p = 0; p < 8; p++) {
                    acc[p] = fma2(tvp[p], w1282, acc[p]);
                    const u64 u2   = tanh2(add2(acc[p], bh2));
                    const u64 phi2 = tanh2(mul2(tw2, tvp[p]));
                    const u64 h2   = *(const u64*)&sm[OFF_HT + (p0 + p) * 264 + 2 * n];
                    const u64 hn2  = fma2(mul2(phi2, zz2[p]), sub2(u2, h2), h2);
                    *(u64*)&sm[OFF_HT + (p0 + p) * 264 + 2 * n] = hn2;
                    if (l == 1) {
                        float lo, hi; up2(hn2, lo, hi);
                        const size_t rg = row0 + 2 * (p0 + p);
                        hids[(rg * T_STEPS + ti) * (size_t)HH + n] = lo;
                        hids[((rg + 1) * T_STEPS + ti) * (size_t)HH + n] = hi;
                    }
                }
            }
        }

        // =================== GRU: gh gates + gi ===================
        u64 g_r[8], g_z[8], g_in[8], g_hn[8];
        {
            const float b_r  = sm[OFF_BIH + n] + sm[OFF_BHH + n];
            const float b_z  = sm[OFF_BIH + 128 + n] + sm[OFF_BHH + 128 + n];
            const float b_in = sm[OFF_BIH + 256 + n];
            const float b_hn = sm[OFF_BHH + 256 + n];
#pragma unroll
            for (int p = 0; p < 8; p++) {
                g_r[p] = pk2(b_r, b_r); g_z[p] = pk2(b_z, b_z);
                g_in[p] = pk2(b_in, b_in); g_hn[p] = pk2(b_hn, b_hn);
            }
        }
        // ghr (phase 6)
        CP_WAIT0(); __syncthreads();
        stage_matrix(7, sm, tid, fWr, fWz, fWh, Whh, Wih); CP_COMMIT();
        pass_nk(sm + 0 * SLOT, htaddr, n, g_r);
        // ghz (phase 7)
        CP_WAIT0(); __syncthreads();
        stage_matrix(8, sm, tid, fWr, fWz, fWh, Whh, Wih); CP_COMMIT();
        pass_nk(sm + 1 * SLOT, htaddr, n, g_z);
        // ghn (phase 8)
        CP_WAIT0(); __syncthreads();
        stage_matrix(9, sm, tid, fWr, fWz, fWh, Whh, Wih); CP_COMMIT();
        pass_nk(sm + 0 * SLOT, htaddr, n, g_hn);
        // gi (phase 9) + combine + decoder
        CP_WAIT0(); __syncthreads();
        stage_matrix(0, sm, tid, fWr, fWz, fWh, Whh, Wih); CP_COMMIT();  // next step's Wr0
        {
            const float* sW = sm + 1 * SLOT;
            for (int k = 0; k < 40; k += 4) {
                const float4 wr = *(const float4*)&sW[n * 44 + k];
                const float4 wz = *(const float4*)&sW[(128 + n) * 44 + k];
                const float4 wn = *(const float4*)&sW[(256 + n) * 44 + k];
                const u64 wra = pk2(wr.x, wr.x), wrb = pk2(wr.y, wr.y), wrc = pk2(wr.z, wr.z), wrd = pk2(wr.w, wr.w);
                const u64 wza = pk2(wz.x, wz.x), wzb = pk2(wz.y, wz.y), wzc = pk2(wz.z, wz.z), wzd = pk2(wz.w, wz.w);
                const u64 wna = pk2(wn.x, wn.x), wnb = pk2(wn.y, wn.y), wnc = pk2(wn.z, wn.z), wnd = pk2(wn.w, wn.w);
#pragma unroll
                for (int p = 0; p < 8; p++) {
                    u64 x0, x1, x2, x3;
                    lds2x64(x0, x1, xtaddr + p * 352 + k * 8);
                    lds2x64(x2, x3, xtaddr + p * 352 + k * 8 + 16);
                    g_r[p]  = fma2(x0, wra, g_r[p]);  g_r[p]  = fma2(x1, wrb, g_r[p]);
                    g_r[p]  = fma2(x2, wrc, g_r[p]);  g_r[p]  = fma2(x3, wrd, g_r[p]);
                    g_z[p]  = fma2(x0, wza, g_z[p]);  g_z[p]  = fma2(x1, wzb, g_z[p]);
                    g_z[p]  = fma2(x2, wzc, g_z[p]);  g_z[p]  = fma2(x3, wzd, g_z[p]);
                    g_in[p] = fma2(x0, wna, g_in[p]); g_in[p] = fma2(x1, wnb, g_in[p]);
                    g_in[p] = fma2(x2, wnc, g_in[p]); g_in[p] = fma2(x3, wnd, g_in[p]);
                }
            }
            // combine: h' = nn + z*(h - nn)
#pragma unroll
            for (int p = 0; p < 8; p++) {
                float rx, ry, zx, zy;
                up2(g_r[p], rx, ry); up2(g_z[p], zx, zy);
                const u64 r2 = pk2(siga(rx), siga(ry));
                const u64 z2 = pk2(siga(zx), siga(zy));
                const u64 nn2 = tanh2(fma2(r2, g_hn[p], g_in[p]));
                const u64 h2 = *(const u64*)&sm[OFF_HT + (p0 + p) * 264 + 2 * n];
                const u64 hn2 = fma2(z2, sub2(h2, nn2), nn2);
                *(u64*)&sm[OFF_HT + (p0 + p) * 264 + 2 * n] = hn2;
            }
        }
        __syncthreads();   // h_new visible for decoder (cross-thread reads)

        // =================== decoder ===================
        {
            const int d = tid & 31, grp = tid >> 5;   // warp-uniform grp
            const float db = sm[OFF_DB + d];
            u64 o0 = pk2(db, db), o1 = pk2(db, db);
            const unsigned xa0 = sbase + (OFF_HT + (2 * grp) * 264) * 4;
            const unsigned xa1 = xa0 + 264 * 4;
            for (int k = 0; k < 128; k += 4) {
                const float4 w = *(const float4*)&sm[OFF_DEC + d * 132 + k];
                const u64 wa = pk2(w.x, w.x), wb = pk2(w.y, w.y);
                const u64 wc = pk2(w.z, w.z), wd = pk2(w.w, w.w);
                u64 x0, x1, x2, x3;
                lds2x64(x0, x1, xa0 + k * 8);
                lds2x64(x2, x3, xa0 + k * 8 + 16);
                o0 = fma2(x0, wa, o0); o0 = fma2(x1, wb, o0);
                o0 = fma2(x2, wc, o0); o0 = fma2(x3, wd, o0);
                lds2x64(x0, x1, xa1 + k * 8);
                lds2x64(x2, x3, xa1 + k * 8 + 16);
                o1 = fma2(x0, wa, o1); o1 = fma2(x1, wb, o1);
                o1 = fma2(x2, wc, o1); o1 = fma2(x3, wd, o1);
            }
            float v0, v1, v2, v3;
            up2(o0, v0, v1); up2(o1, v2, v3);
            const size_t r0g = row0 + 4 * grp;
            outs[((r0g + 0) * T_STEPS + ti) * (size_t)DS + d] = v0;
            outs[((r0g + 1) * T_STEPS + ti) * (size_t)DS + d] = v1;
            outs[((r0g + 2) * T_STEPS + ti) * (size_t)DS + d] = v2;
            outs[((r0g + 3) * T_STEPS + ti) * (size_t)DS + d] = v3;
        }
    }
}

extern "C" void kernel_launch(void* const* d_in, const int* in_sizes, int n_in,
                              void* d_out, int out_size)
{
    const float* s    = (const float*)d_in[0];
    const float* a    = (const float*)d_in[1];
    const float* t    = (const float*)d_in[2];
    const float* fWr  = (const float*)d_in[3];
    const float* fbr  = (const float*)d_in[4];
    const float* fWz  = (const float*)d_in[5];
    const float* fbz  = (const float*)d_in[6];
    const float* fWh  = (const float*)d_in[7];
    const float* fbh  = (const float*)d_in[8];
    const float* ftw  = (const float*)d_in[9];
    const float* Wih  = (const float*)d_in[10];
    const float* Whh  = (const float*)d_in[11];
    const float* bih  = (const float*)d_in[12];
    const float* bhh  = (const float*)d_in[13];
    const float* decW = (const float*)d_in[14];
    const float* decb = (const float*)d_in[15];

    float* outs = (float*)d_out;
    float* hids = outs + (size_t)4096 * T_STEPS * DS;

    const int SMEM = SMEM_FL * 4;
    cudaFuncSetAttribute(odernn_persistent, cudaFuncAttributeMaxDynamicSharedMemorySize, SMEM);
    odernn_persistent<<<128, NTHR, SMEM>>>(s, a, t, fWr, fbr, fWz, fbz, fWh, fbh, ftw,
                                           Wih, Whh, bih, bhh, decW, decb, outs, hids);
}

// round 5
// speedup vs baseline: 2.1658x; 1.1813x over previous
#include <cuda_runtime.h>
#include <stddef.h>

#define T_STEPS 200
#define DS 32
#define DA 8
#define HH 128
#define NTHR 256

typedef unsigned long long u64;

// ---- smem layout (float offsets) ----
#define SLOT    16896            // staging slot size (floats)
#define OFF_DEC 33792            // dec [d][k] pad 132  (32*132)
#define OFF_HT  38016            // h   [pair][k] float2, stride 264 fl (16*264)
#define OFF_RH  42240            // r*h same layout
#define OFF_XT  46464            // gru x [pair][k<40] float2, stride 88 (16*88)
#define OFF_FB  47872            // flow biases [l*512 + part*128 + n]
#define OFF_BIH 48896            // 384
#define OFF_BHH 49280            // 384
#define OFF_DB  49664            // 32
#define OFF_TV  49696            // 32
#define SMEM_FL 49728            // *4 = 198912 bytes

// ---- packed helpers ----
__device__ __forceinline__ u64 pk2(float lo, float hi) {
    u64 r; asm("mov.b64 %0,{%1,%2};" : "=l"(r) : "f"(lo), "f"(hi)); return r;
}
__device__ __forceinline__ void up2(u64 v, float& lo, float& hi) {
    asm("mov.b64 {%0,%1},%2;" : "=f"(lo), "=f"(hi) : "l"(v));
}
__device__ __forceinline__ u64 fma2(u64 a, u64 b, u64 c) {
    u64 d; asm("fma.rn.f32x2 %0,%1,%2,%3;" : "=l"(d) : "l"(a), "l"(b), "l"(c)); return d;
}
__device__ __forceinline__ u64 mul2(u64 a, u64 b) {
    u64 d; asm("mul.rn.f32x2 %0,%1,%2;" : "=l"(d) : "l"(a), "l"(b)); return d;
}
__device__ __forceinline__ u64 add2(u64 a, u64 b) {
    u64 d; asm("add.rn.f32x2 %0,%1,%2;" : "=l"(d) : "l"(a), "l"(b)); return d;
}
__device__ __forceinline__ u64 sub2(u64 a, u64 b) { float x,y,p,q; up2(a,x,y); up2(b,p,q); return pk2(x-p, y-q); }
__device__ __forceinline__ void lds2x64(u64& a, u64& b, unsigned addr) {
    asm volatile("ld.shared.v2.b64 {%0,%1},[%2];" : "=l"(a), "=l"(b) : "r"(addr));
}
__device__ __forceinline__ float tanha(float x) {
    float y; asm("tanh.approx.f32 %0,%1;" : "=f"(y) : "f"(x)); return y;
}
__device__ __forceinline__ float siga(float x) { return fmaf(0.5f, tanha(0.5f * x), 0.5f); }
__device__ __forceinline__ u64 tanh2(u64 v) { float a, b; up2(v, a, b); return pk2(tanha(a), tanha(b)); }

__device__ __forceinline__ void cpa16(float* dst, const float* src) {
    unsigned d = (unsigned)__cvta_generic_to_shared(dst);
    asm volatile("cp.async.cg.shared.global [%0], [%1], 16;" :: "r"(d), "l"(src));
}
#define CP_COMMIT() asm volatile("cp.async.commit_group;" ::: "memory")
#define CP_WAIT0()  asm volatile("cp.async.wait_group 0;" ::: "memory")

// stage matrix for phase ph into slot ph&1
// phases: 0..5 flow (Wr0,Wz0,Wh0,Wr1,Wz1,Wh1) [k][n] contiguous
//         6..8 Whh gates [n][k] pad 132 ; 9 Wih [n][k] pad 44
__device__ __forceinline__ void stage_matrix(int ph, float* sm, int tid,
    const float* fWr, const float* fWz, const float* fWh,
    const float* Whh, const float* Wih)
{
    float* dst = sm + (ph & 1) * SLOT;
    if (ph < 6) {
        const int l = ph / 3, w = ph % 3;
        const float* src = (w == 0 ? fWr : (w == 1 ? fWz : fWh)) + (size_t)l * 129 * 128;
        for (int i = tid; i < 4128; i += NTHR) cpa16(dst + i * 4, src + i * 4);
    } else if (ph < 9) {
        const float* src = Whh + (size_t)(ph - 6) * 128 * 128;
        for (int i = tid; i < 4096; i += NTHR) {
            int r = i >> 5, c = i & 31;
            cpa16(dst + r * 132 + c * 4, src + r * 128 + c * 4);
        }
    } else {
        for (int i = tid; i < 3840; i += NTHR) {
            int r = i / 10, c = i - r * 10;
            cpa16(dst + r * 44 + c * 4, Wih + r * 40 + c * 4);
        }
    }
}

// flow pass: weights [k][n], consecutive cols n0,n0+1; x at xaddr (pg-adjusted),
// pairs p_i = 4i+pg. acc[2i+c] accumulates (pair_i, col n0+c).
__device__ __forceinline__ void pass_flow(const float* sW, unsigned xaddr, int n0, u64 acc[8])
{
#pragma unroll 1
    for (int k = 0; k < 128; k += 4) {
        const float2 w0 = *(const float2*)&sW[(k+0)*128 + n0];
        const float2 w1 = *(const float2*)&sW[(k+1)*128 + n0];
        const float2 w2 = *(const float2*)&sW[(k+2)*128 + n0];
        const float2 w3 = *(const float2*)&sW[(k+3)*128 + n0];
        const u64 a0 = pk2(w0.x,w0.x), b0 = pk2(w0.y,w0.y);
        const u64 a1 = pk2(w1.x,w1.x), b1 = pk2(w1.y,w1.y);
        const u64 a2 = pk2(w2.x,w2.x), b2 = pk2(w2.y,w2.y);
        const u64 a3 = pk2(w3.x,w3.x), b3 = pk2(w3.y,w3.y);
#pragma unroll
        for (int i = 0; i < 4; i++) {
            u64 x0,x1,x2,x3;
            lds2x64(x0,x1, xaddr + i*4224 + k*8);
            lds2x64(x2,x3, xaddr + i*4224 + k*8 + 16);
            acc[2*i+0] = fma2(x0,a0,acc[2*i+0]); acc[2*i+1] = fma2(x0,b0,acc[2*i+1]);
            acc[2*i+0] = fma2(x1,a1,acc[2*i+0]); acc[2*i+1] = fma2(x1,b1,acc[2*i+1]);
            acc[2*i+0] = fma2(x2,a2,acc[2*i+0]); acc[2*i+1] = fma2(x2,b2,acc[2*i+1]);
            acc[2*i+0] = fma2(x3,a3,acc[2*i+0]); acc[2*i+1] = fma2(x3,b3,acc[2*i+1]);
        }
    }
}

// gh pass: weights [n][k] pad 132, split cols n0s, n0s+64; x = hT
__device__ __forceinline__ void pass_gh(const float* sW, unsigned xaddr, int n0s, u64 acc[8])
{
#pragma unroll 1
    for (int k = 0; k < 128; k += 4) {
        const float4 wA = *(const float4*)&sW[n0s*132 + k];
        const float4 wB = *(const float4*)&sW[(n0s+64)*132 + k];
        const u64 a0 = pk2(wA.x,wA.x), a1 = pk2(wA.y,wA.y), a2 = pk2(wA.z,wA.z), a3 = pk2(wA.w,wA.w);
        const u64 b0 = pk2(wB.x,wB.x), b1 = pk2(wB.y,wB.y), b2 = pk2(wB.z,wB.z), b3 = pk2(wB.w,wB.w);
#pragma unroll
        for (int i = 0; i < 4; i++) {
            u64 x0,x1,x2,x3;
            lds2x64(x0,x1, xaddr + i*4224 + k*8);
            lds2x64(x2,x3, xaddr + i*4224 + k*8 + 16);
            acc[2*i+0] = fma2(x0,a0,acc[2*i+0]); acc[2*i+1] = fma2(x0,b0,acc[2*i+1]);
            acc[2*i+0] = fma2(x1,a1,acc[2*i+0]); acc[2*i+1] = fma2(x1,b1,acc[2*i+1]);
            acc[2*i+0] = fma2(x2,a2,acc[2*i+0]); acc[2*i+1] = fma2(x2,b2,acc[2*i+1]);
            acc[2*i+0] = fma2(x3,a3,acc[2*i+0]); acc[2*i+1] = fma2(x3,b3,acc[2*i+1]);
        }
    }
}

// gi pass: weights [n][k] pad 44 (one gate block), split cols; x = XT (K=40)
__device__ __forceinline__ void pass_gi(const float* sW, unsigned xaddr, int n0s, u64 acc[8])
{
#pragma unroll 1
    for (int k = 0; k < 40; k += 4) {
        const float4 wA = *(const float4*)&sW[n0s*44 + k];
        const float4 wB = *(const float4*)&sW[(n0s+64)*44 + k];
        const u64 a0 = pk2(wA.x,wA.x), a1 = pk2(wA.y,wA.y), a2 = pk2(wA.z,wA.z), a3 = pk2(wA.w,wA.w);
        const u64 b0 = pk2(wB.x,wB.x), b1 = pk2(wB.y,wB.y), b2 = pk2(wB.z,wB.z), b3 = pk2(wB.w,wB.w);
#pragma unroll
        for (int i = 0; i < 4; i++) {
            u64 x0,x1,x2,x3;
            lds2x64(x0,x1, xaddr + i*1408 + k*8);
            lds2x64(x2,x3, xaddr + i*1408 + k*8 + 16);
            acc[2*i+0] = fma2(x0,a0,acc[2*i+0]); acc[2*i+1] = fma2(x0,b0,acc[2*i+1]);
            acc[2*i+0] = fma2(x1,a1,acc[2*i+0]); acc[2*i+1] = fma2(x1,b1,acc[2*i+1]);
            acc[2*i+0] = fma2(x2,a2,acc[2*i+0]); acc[2*i+1] = fma2(x2,b2,acc[2*i+1]);
            acc[2*i+0] = fma2(x3,a3,acc[2*i+0]); acc[2*i+1] = fma2(x3,b3,acc[2*i+1]);
        }
    }
}

__global__ void __launch_bounds__(NTHR, 1)
odernn_persistent(const float* __restrict__ s,   const float* __restrict__ a,
                  const float* __restrict__ t,
                  const float* __restrict__ fWr, const float* __restrict__ fbr,
                  const float* __restrict__ fWz, const float* __restrict__ fbz,
                  const float* __restrict__ fWh, const float* __restrict__ fbh,
                  const float* __restrict__ ftw,
                  const float* __restrict__ Wih, const float* __restrict__ Whh,
                  const float* __restrict__ bih, const float* __restrict__ bhh,
                  const float* __restrict__ decW, const float* __restrict__ decb,
                  float* __restrict__ outs, float* __restrict__ hids)
{
    extern __shared__ float sm[];
    const int tid  = threadIdx.x;
    const int row0 = blockIdx.x * 32;
    const unsigned sbase = (unsigned)__cvta_generic_to_shared(sm);

    const int w    = tid >> 5;
    const int lane = tid & 31;
    const int pg   = lane >> 3;          // pair-group 0..3 (pairs 4i+pg)
    const int cg   = lane & 7;           // col-group 0..7
    const int n0c  = w * 16 + cg * 2;    // consecutive cols (flow)
    const int n0s  = w * 8 + cg;         // split cols n0s, n0s+64 (GRU)

    const unsigned htaddr = sbase + OFF_HT * 4 + pg * 1056;
    const unsigned rhaddr = sbase + OFF_RH * 4 + pg * 1056;
    const unsigned xtaddr = sbase + OFF_XT * 4 + pg * 352;

    // ---- one-time init ----
    for (int i = tid; i < 16 * 264; i += NTHR) sm[OFF_HT + i] = 0.0f;
    if (tid < 128) {
#pragma unroll
        for (int l = 0; l < 2; l++) {
            sm[OFF_FB + l * 512 +   0 + tid] = fbr[l * HH + tid];
            sm[OFF_FB + l * 512 + 128 + tid] = fbz[l * HH + tid];
            sm[OFF_FB + l * 512 + 256 + tid] = fbh[l * HH + tid];
            sm[OFF_FB + l * 512 + 384 + tid] = ftw[l * HH + tid];
        }
    }
    for (int i = tid; i < 384; i += NTHR) { sm[OFF_BIH + i] = bih[i]; sm[OFF_BHH + i] = bhh[i]; }
    if (tid < 32) sm[OFF_DB + tid] = decb[tid];
    for (int i = tid; i < 1024; i += NTHR) {       // dec [d][k] pad 132
        int r = i >> 5, c = i & 31;
        cpa16(sm + OFF_DEC + r * 132 + c * 4, decW + r * 128 + c * 4);
    }
    stage_matrix(0, sm, tid, fWr, fWz, fWh, Whh, Wih);
    CP_COMMIT();

    for (int ti = 0; ti < T_STEPS; ti++) {
        if (tid < 32) sm[OFF_TV + tid] = t[(size_t)(row0 + tid) * T_STEPS + ti];
        for (int i = tid; i < 32 * 40; i += NTHR) {
            const int m = i / 40, c = i - m * 40;
            const size_t row = row0 + m;
            const float v = (c < DS) ? s[(row * T_STEPS + ti) * DS + c]
                                     : a[(row * T_STEPS + ti) * DA + (c - DS)];
            sm[OFF_XT + (m >> 1) * 88 + 2 * c + (m & 1)] = v;
        }

        u64 zz[8], tvp[4];

        // =================== flow layers ===================
#pragma unroll 1
        for (int l = 0; l < 2; l++) {
            const int phb = l * 3;
            const float* bias = sm + OFF_FB + l * 512;

            // ---- pass r ----
            CP_WAIT0(); __syncthreads();
            stage_matrix(phb + 1, sm, tid, fWr, fWz, fWh, Whh, Wih); CP_COMMIT();
            {
                const float* sW = sm + (phb & 1) * SLOT;
#pragma unroll
                for (int i = 0; i < 4; i++) {
                    const int p = 4 * i + pg;
                    tvp[i] = pk2(sm[OFF_TV + 2 * p], sm[OFF_TV + 2 * p + 1]);
                }
                u64 acc[8];
#pragma unroll
                for (int q = 0; q < 8; q++) acc[q] = 0ULL;
                pass_flow(sW, htaddr, n0c, acc);
                const float2 wt = *(const float2*)&sW[128 * 128 + n0c];
                const u64 wta = pk2(wt.x, wt.x), wtb = pk2(wt.y, wt.y);
                const float br0 = bias[n0c], br1 = bias[n0c + 1];
#pragma unroll
                for (int i = 0; i < 4; i++) {
                    const int p = 4 * i + pg;
                    u64 a0 = fma2(tvp[i], wta, acc[2*i+0]);
                    u64 a1 = fma2(tvp[i], wtb, acc[2*i+1]);
                    float x, y;
                    up2(a0, x, y);
                    const u64 rr0 = pk2(0.8f * siga(x + br0), 0.8f * siga(y + br0));
                    up2(a1, x, y);
                    const u64 rr1 = pk2(0.8f * siga(x + br1), 0.8f * siga(y + br1));
                    const u64 h0 = *(const u64*)&sm[OFF_HT + p * 264 + 2 * n0c];
                    const u64 h1 = *(const u64*)&sm[OFF_HT + p * 264 + 2 * n0c + 2];
                    *(u64*)&sm[OFF_RH + p * 264 + 2 * n0c]     = mul2(rr0, h0);
                    *(u64*)&sm[OFF_RH + p * 264 + 2 * n0c + 2] = mul2(rr1, h1);
                }
            }

            // ---- pass z ----
            CP_WAIT0(); __syncthreads();
            stage_matrix(phb + 2, sm, tid, fWr, fWz, fWh, Whh, Wih); CP_COMMIT();
            {
                const float* sW = sm + ((phb + 1) & 1) * SLOT;
                u64 acc[8];
#pragma unroll
                for (int q = 0; q < 8; q++) acc[q] = 0ULL;
                pass_flow(sW, htaddr, n0c, acc);
                const float2 wt = *(const float2*)&sW[128 * 128 + n0c];
                const u64 wta = pk2(wt.x, wt.x), wtb = pk2(wt.y, wt.y);
                const float bz0 = bias[128 + n0c], bz1 = bias[128 + n0c + 1];
#pragma unroll
                for (int i = 0; i < 4; i++) {
                    u64 a0 = fma2(tvp[i], wta, acc[2*i+0]);
                    u64 a1 = fma2(tvp[i], wtb, acc[2*i+1]);
                    float x, y;
                    up2(a0, x, y); zz[2*i+0] = pk2(0.4f * siga(x + bz0), 0.4f * siga(y + bz0));
                    up2(a1, x, y); zz[2*i+1] = pk2(0.4f * siga(x + bz1), 0.4f * siga(y + bz1));
                }
            }

            // ---- pass u + combine ----
            CP_WAIT0(); __syncthreads();
            {
                stage_matrix(phb + 3, sm, tid, fWr, fWz, fWh, Whh, Wih); CP_COMMIT();
                const float* sW = sm + ((phb + 2) & 1) * SLOT;
                u64 acc[8];
#pragma unroll
                for (int q = 0; q < 8; q++) acc[q] = 0ULL;
                pass_flow(sW, rhaddr, n0c, acc);
                const float2 wt = *(const float2*)&sW[128 * 128 + n0c];
                const u64 wta = pk2(wt.x, wt.x), wtb = pk2(wt.y, wt.y);
                const float bh0 = bias[256 + n0c], bh1 = bias[256 + n0c + 1];
                const float tw0 = bias[384 + n0c], tw1 = bias[384 + n0c + 1];
                const u64 bh20 = pk2(bh0, bh0), bh21 = pk2(bh1, bh1);
                const u64 tw20 = pk2(tw0, tw0), tw21 = pk2(tw1, tw1);
#pragma unroll
                for (int i = 0; i < 4; i++) {
                    const int p = 4 * i + pg;
                    const u64 u0   = tanh2(add2(fma2(tvp[i], wta, acc[2*i+0]), bh20));
                    const u64 u1   = tanh2(add2(fma2(tvp[i], wtb, acc[2*i+1]), bh21));
                    const u64 phi0 = tanh2(mul2(tw20, tvp[i]));
                    const u64 phi1 = tanh2(mul2(tw21, tvp[i]));
                    const u64 h0 = *(const u64*)&sm[OFF_HT + p * 264 + 2 * n0c];
                    const u64 h1 = *(const u64*)&sm[OFF_HT + p * 264 + 2 * n0c + 2];
                    const u64 hn0 = fma2(mul2(phi0, zz[2*i+0]), sub2(u0, h0), h0);
                    const u64 hn1 = fma2(mul2(phi1, zz[2*i+1]), sub2(u1, h1), h1);
                    *(u64*)&sm[OFF_HT + p * 264 + 2 * n0c]     = hn0;
                    *(u64*)&sm[OFF_HT + p * 264 + 2 * n0c + 2] = hn1;
                    if (l == 1) {
                        float a0lo, a0hi, a1lo, a1hi;
                        up2(hn0, a0lo, a0hi); up2(hn1, a1lo, a1hi);
                        const size_t rg = row0 + 2 * p;
                        *(float2*)&hids[(rg * T_STEPS + ti) * (size_t)HH + n0c]       = make_float2(a0lo, a1lo);
                        *(float2*)&hids[((rg + 1) * T_STEPS + ti) * (size_t)HH + n0c] = make_float2(a0hi, a1hi);
                    }
                }
            }
        }

        // =================== GRU ===================
        u64 g_r[8], g_z[8], g_in[8], g_hn[8];
        {
            const float br0 = sm[OFF_BIH + n0s] + sm[OFF_BHH + n0s];
            const float br1 = sm[OFF_BIH + n0s + 64] + sm[OFF_BHH + n0s + 64];
            const float bz0 = sm[OFF_BIH + 128 + n0s] + sm[OFF_BHH + 128 + n0s];
            const float bz1 = sm[OFF_BIH + 128 + n0s + 64] + sm[OFF_BHH + 128 + n0s + 64];
            const float bi0 = sm[OFF_BIH + 256 + n0s],      bi1 = sm[OFF_BIH + 256 + n0s + 64];
            const float bn0 = sm[OFF_BHH + 256 + n0s],      bn1 = sm[OFF_BHH + 256 + n0s + 64];
#pragma unroll
            for (int i = 0; i < 4; i++) {
                g_r[2*i+0] = pk2(br0, br0); g_r[2*i+1] = pk2(br1, br1);
                g_z[2*i+0] = pk2(bz0, bz0); g_z[2*i+1] = pk2(bz1, bz1);
                g_in[2*i+0] = pk2(bi0, bi0); g_in[2*i+1] = pk2(bi1, bi1);
                g_hn[2*i+0] = pk2(bn0, bn0); g_hn[2*i+1] = pk2(bn1, bn1);
            }
        }
        // ghr (phase 6, slot 0)
        CP_WAIT0(); __syncthreads();
        stage_matrix(7, sm, tid, fWr, fWz, fWh, Whh, Wih); CP_COMMIT();
        pass_gh(sm + 0 * SLOT, htaddr, n0s, g_r);
        // ghz (phase 7, slot 1)
        CP_WAIT0(); __syncthreads();
        stage_matrix(8, sm, tid, fWr, fWz, fWh, Whh, Wih); CP_COMMIT();
        pass_gh(sm + 1 * SLOT, htaddr, n0s, g_z);
        // ghn (phase 8, slot 0)
        CP_WAIT0(); __syncthreads();
        stage_matrix(9, sm, tid, fWr, fWz, fWh, Whh, Wih); CP_COMMIT();
        pass_gh(sm + 0 * SLOT, htaddr, n0s, g_hn);
        // gi (phase 9, slot 1) + combine
        CP_WAIT0(); __syncthreads();
        stage_matrix(0, sm, tid, fWr, fWz, fWh, Whh, Wih); CP_COMMIT();   // next step Wr0
        {
            const float* sW = sm + 1 * SLOT;
            pass_gi(sW,            xtaddr, n0s, g_r);
            pass_gi(sW + 128 * 44, xtaddr, n0s, g_z);
            pass_gi(sW + 256 * 44, xtaddr, n0s, g_in);
#pragma unroll
            for (int i = 0; i < 4; i++) {
                const int p = 4 * i + pg;
#pragma unroll
                for (int c = 0; c < 2; c++) {
                    const int n = n0s + 64 * c;
                    float rx, ry, zx, zy;
                    up2(g_r[2*i+c], rx, ry); up2(g_z[2*i+c], zx, zy);
                    const u64 r2 = pk2(siga(rx), siga(ry));
                    const u64 z2 = pk2(siga(zx), siga(zy));
                    const u64 nn2 = tanh2(fma2(r2, g_hn[2*i+c], g_in[2*i+c]));
                    const u64 h2 = *(const u64*)&sm[OFF_HT + p * 264 + 2 * n];
                    const u64 hn2 = fma2(z2, sub2(h2, nn2), nn2);
                    *(u64*)&sm[OFF_HT + p * 264 + 2 * n] = hn2;
                }
            }
        }
        __syncthreads();   // h_new visible for decoder

        // =================== decoder ===================
        {
            const int d = tid & 31, grp = tid >> 5;
            const float db = sm[OFF_DB + d];
            u64 o0 = pk2(db, db), o1 = pk2(db, db);
            const unsigned xa0 = sbase + (OFF_HT + (2 * grp) * 264) * 4;
            const unsigned xa1 = xa0 + 264 * 4;
            for (int k = 0; k < 128; k += 4) {
                const float4 wv = *(const float4*)&sm[OFF_DEC + d * 132 + k];
                const u64 wa = pk2(wv.x, wv.x), wb = pk2(wv.y, wv.y);
                const u64 wc = pk2(wv.z, wv.z), wd = pk2(wv.w, wv.w);
                u64 x0, x1, x2, x3;
                lds2x64(x0, x1, xa0 + k * 8);
                lds2x64(x2, x3, xa0 + k * 8 + 16);
                o0 = fma2(x0, wa, o0); o0 = fma2(x1, wb, o0);
                o0 = fma2(x2, wc, o0); o0 = fma2(x3, wd, o0);
                lds2x64(x0, x1, xa1 + k * 8);
                lds2x64(x2, x3, xa1 + k * 8 + 16);
                o1 = fma2(x0, wa, o1); o1 = fma2(x1, wb, o1);
                o1 = fma2(x2, wc, o1); o1 = fma2(x3, wd, o1);
            }
            float v0, v1, v2, v3;
            up2(o0, v0, v1); up2(o1, v2, v3);
            const size_t r0g = row0 + 4 * grp;
            outs[((r0g + 0) * T_STEPS + ti) * (size_t)DS + d] = v0;
            outs[((r0g + 1) * T_STEPS + ti) * (size_t)DS + d] = v1;
            outs[((r0g + 2) * T_STEPS + ti) * (size_t)DS + d] = v2;
            outs[((r0g + 3) * T_STEPS + ti) * (size_t)DS + d] = v3;
        }
    }
}

extern "C" void kernel_launch(void* const* d_in, const int* in_sizes, int n_in,
                              void* d_out, int out_size)
{
    const float* s    = (const float*)d_in[0];
    const float* a    = (const float*)d_in[1];
    const float* t    = (const float*)d_in[2];
    const float* fWr  = (const float*)d_in[3];
    const float* fbr  = (const float*)d_in[4];
    const float* fWz  = (const float*)d_in[5];
    const float* fbz  = (const float*)d_in[6];
    const float* fWh  = (const float*)d_in[7];
    const float* fbh  = (const float*)d_in[8];
    const float* ftw  = (const float*)d_in[9];
    const float* Wih  = (const float*)d_in[10];
    const float* Whh  = (const float*)d_in[11];
    const float* bih  = (const float*)d_in[12];
    const float* bhh  = (const float*)d_in[13];
    const float* decW = (const float*)d_in[14];
    const float* decb = (const float*)d_in[15];

    float* outs = (float*)d_out;
    float* hids = outs + (size_t)4096 * T_STEPS * DS;

    const int SMEM = SMEM_FL * 4;
    cudaFuncSetAttribute(odernn_persistent, cudaFuncAttributeMaxDynamicSharedMemorySize, SMEM);
    odernn_persistent<<<128, NTHR, SMEM>>>(s, a, t, fWr, fbr, fWz, fbz, fWh, fbh, ftw,
                                           Wih, Whh, bih, bhh, decW, decb, outs, hids);
}

// round 6
// speedup vs baseline: 2.2842x; 1.0547x over previous
#include <cuda_runtime.h>
#include <stddef.h>

#define T_STEPS 200
#define DS 32
#define DA 8
#define HH 128
#define NTHR 256

typedef unsigned long long u64;

// ---- smem layout (float offsets) ----
#define SLOT    16896            // staging slot size (floats)
#define OFF_DEC 33792            // dec [d][k] pad 132  (32*132)
#define OFF_HT  38016            // h   [pair][k] float2, stride 264 fl (16*264)
#define OFF_RH  42240            // r*h same layout
#define OFF_XT  46464            // gru x [pair][k<40] float2, stride 88 (16*88)
#define OFF_FB  47872            // flow biases [l*512 + part*128 + n]
#define OFF_BIH 48896            // 384
#define OFF_BHH 49280            // 384
#define OFF_DB  49664            // 32
#define OFF_TV  49696            // 32
#define SMEM_FL 49728            // *4 = 198912 bytes

// ---- packed helpers ----
__device__ __forceinline__ u64 pk2(float lo, float hi) {
    u64 r; asm("mov.b64 %0,{%1,%2};" : "=l"(r) : "f"(lo), "f"(hi)); return r;
}
__device__ __forceinline__ void up2(u64 v, float& lo, float& hi) {
    asm("mov.b64 {%0,%1},%2;" : "=f"(lo), "=f"(hi) : "l"(v));
}
__device__ __forceinline__ u64 fma2(u64 a, u64 b, u64 c) {
    u64 d; asm("fma.rn.f32x2 %0,%1,%2,%3;" : "=l"(d) : "l"(a), "l"(b), "l"(c)); return d;
}
__device__ __forceinline__ u64 mul2(u64 a, u64 b) {
    u64 d; asm("mul.rn.f32x2 %0,%1,%2;" : "=l"(d) : "l"(a), "l"(b)); return d;
}
__device__ __forceinline__ u64 add2(u64 a, u64 b) {
    u64 d; asm("add.rn.f32x2 %0,%1,%2;" : "=l"(d) : "l"(a), "l"(b)); return d;
}
__device__ __forceinline__ u64 sub2(u64 a, u64 b) { float x,y,p,q; up2(a,x,y); up2(b,p,q); return pk2(x-p, y-q); }
__device__ __forceinline__ float tanha(float x) {
    float y; asm("tanh.approx.f32 %0,%1;" : "=f"(y) : "f"(x)); return y;
}
__device__ __forceinline__ float siga(float x) { return fmaf(0.5f, tanha(0.5f * x), 0.5f); }
__device__ __forceinline__ u64 tanh2(u64 v) { float a, b; up2(v, a, b); return pk2(tanha(a), tanha(b)); }

// plain (schedulable) 128-bit shared loads: two packed f32x2 values
#define LDX2(x0, x1, ptr) do { \
    const ulonglong2 _v = *reinterpret_cast<const ulonglong2*>(ptr); \
    (x0) = _v.x; (x1) = _v.y; } while (0)

__device__ __forceinline__ void cpa16(float* dst, const float* src) {
    unsigned d = (unsigned)__cvta_generic_to_shared(dst);
    asm volatile("cp.async.cg.shared.global [%0], [%1], 16;" :: "r"(d), "l"(src));
}
#define CP_COMMIT() asm volatile("cp.async.commit_group;" ::: "memory")
#define CP_WAIT0()  asm volatile("cp.async.wait_group 0;" ::: "memory")

// stage matrix for phase ph into slot ph&1
// phases: 0..5 flow (Wr0,Wz0,Wh0,Wr1,Wz1,Wh1) [k][n] contiguous
//         6..8 Whh gates [n][k] pad 132 ; 9 Wih [n][k] pad 44
__device__ __forceinline__ void stage_matrix(int ph, float* sm, int tid,
    const float* fWr, const float* fWz, const float* fWh,
    const float* Whh, const float* Wih)
{
    float* dst = sm + (ph & 1) * SLOT;
    if (ph < 6) {
        const int l = ph / 3, w = ph % 3;
        const float* src = (w == 0 ? fWr : (w == 1 ? fWz : fWh)) + (size_t)l * 129 * 128;
        for (int i = tid; i < 4128; i += NTHR) cpa16(dst + i * 4, src + i * 4);
    } else if (ph < 9) {
        const float* src = Whh + (size_t)(ph - 6) * 128 * 128;
        for (int i = tid; i < 4096; i += NTHR) {
            int r = i >> 5, c = i & 31;
            cpa16(dst + r * 132 + c * 4, src + r * 128 + c * 4);
        }
    } else {
        for (int i = tid; i < 3840; i += NTHR) {
            int r = i / 10, c = i - r * 10;
            cpa16(dst + r * 44 + c * 4, Wih + r * 40 + c * 4);
        }
    }
}

// flow pass: weights [k][n], consecutive cols n0,n0+1; x rows [pair][k] f32x2,
// thread covers pairs 4i+pg via xb = &sm[OFF_HT] + pg*264. acc[2i+c].
__device__ __forceinline__ void pass_flow(const float* sW, const float* xb, int n0, u64 acc[8])
{
#pragma unroll 2
    for (int k = 0; k < 128; k += 4) {
        const float2 w0 = *(const float2*)&sW[(k+0)*128 + n0];
        const float2 w1 = *(const float2*)&sW[(k+1)*128 + n0];
        const float2 w2 = *(const float2*)&sW[(k+2)*128 + n0];
        const float2 w3 = *(const float2*)&sW[(k+3)*128 + n0];
        const u64 a0 = pk2(w0.x,w0.x), b0 = pk2(w0.y,w0.y);
        const u64 a1 = pk2(w1.x,w1.x), b1 = pk2(w1.y,w1.y);
        const u64 a2 = pk2(w2.x,w2.x), b2 = pk2(w2.y,w2.y);
        const u64 a3 = pk2(w3.x,w3.x), b3 = pk2(w3.y,w3.y);
#pragma unroll
        for (int i = 0; i < 4; i++) {
            u64 x0,x1,x2,x3;
            LDX2(x0,x1, xb + i*1056 + k*2);
            LDX2(x2,x3, xb + i*1056 + k*2 + 4);
            acc[2*i+0] = fma2(x0,a0,acc[2*i+0]); acc[2*i+1] = fma2(x0,b0,acc[2*i+1]);
            acc[2*i+0] = fma2(x1,a1,acc[2*i+0]); acc[2*i+1] = fma2(x1,b1,acc[2*i+1]);
            acc[2*i+0] = fma2(x2,a2,acc[2*i+0]); acc[2*i+1] = fma2(x2,b2,acc[2*i+1]);
            acc[2*i+0] = fma2(x3,a3,acc[2*i+0]); acc[2*i+1] = fma2(x3,b3,acc[2*i+1]);
        }
    }
}

// gh pass: weights [n][k] pad 132, split cols n0s, n0s+64; x = hT
__device__ __forceinline__ void pass_gh(const float* sW, const float* xb, int n0s, u64 acc[8])
{
#pragma unroll 2
    for (int k = 0; k < 128; k += 4) {
        const float4 wA = *(const float4*)&sW[n0s*132 + k];
        const float4 wB = *(const float4*)&sW[(n0s+64)*132 + k];
        const u64 a0 = pk2(wA.x,wA.x), a1 = pk2(wA.y,wA.y), a2 = pk2(wA.z,wA.z), a3 = pk2(wA.w,wA.w);
        const u64 b0 = pk2(wB.x,wB.x), b1 = pk2(wB.y,wB.y), b2 = pk2(wB.z,wB.z), b3 = pk2(wB.w,wB.w);
#pragma unroll
        for (int i = 0; i < 4; i++) {
            u64 x0,x1,x2,x3;
            LDX2(x0,x1, xb + i*1056 + k*2);
            LDX2(x2,x3, xb + i*1056 + k*2 + 4);
            acc[2*i+0] = fma2(x0,a0,acc[2*i+0]); acc[2*i+1] = fma2(x0,b0,acc[2*i+1]);
            acc[2*i+0] = fma2(x1,a1,acc[2*i+0]); acc[2*i+1] = fma2(x1,b1,acc[2*i+1]);
            acc[2*i+0] = fma2(x2,a2,acc[2*i+0]); acc[2*i+1] = fma2(x2,b2,acc[2*i+1]);
            acc[2*i+0] = fma2(x3,a3,acc[2*i+0]); acc[2*i+1] = fma2(x3,b3,acc[2*i+1]);
        }
    }
}

// gi pass: weights [n][k] pad 44 (one gate block), split cols; x = XT (K=40)
__device__ __forceinline__ void pass_gi(const float* sW, const float* xb, int n0s, u64 acc[8])
{
#pragma unroll 2
    for (int k = 0; k < 40; k += 4) {
        const float4 wA = *(const float4*)&sW[n0s*44 + k];
        const float4 wB = *(const float4*)&sW[(n0s+64)*44 + k];
        const u64 a0 = pk2(wA.x,wA.x), a1 = pk2(wA.y,wA.y), a2 = pk2(wA.z,wA.z), a3 = pk2(wA.w,wA.w);
        const u64 b0 = pk2(wB.x,wB.x), b1 = pk2(wB.y,wB.y), b2 = pk2(wB.z,wB.z), b3 = pk2(wB.w,wB.w);
#pragma unroll
        for (int i = 0; i < 4; i++) {
            u64 x0,x1,x2,x3;
            LDX2(x0,x1, xb + i*352 + k*2);
            LDX2(x2,x3, xb + i*352 + k*2 + 4);
            acc[2*i+0] = fma2(x0,a0,acc[2*i+0]); acc[2*i+1] = fma2(x0,b0,acc[2*i+1]);
            acc[2*i+0] = fma2(x1,a1,acc[2*i+0]); acc[2*i+1] = fma2(x1,b1,acc[2*i+1]);
            acc[2*i+0] = fma2(x2,a2,acc[2*i+0]); acc[2*i+1] = fma2(x2,b2,acc[2*i+1]);
            acc[2*i+0] = fma2(x3,a3,acc[2*i+0]); acc[2*i+1] = fma2(x3,b3,acc[2*i+1]);
        }
    }
}

__global__ void __launch_bounds__(NTHR, 1)
odernn_persistent(const float* __restrict__ s,   const float* __restrict__ a,
                  const float* __restrict__ t,
                  const float* __restrict__ fWr, const float* __restrict__ fbr,
                  const float* __restrict__ fWz, const float* __restrict__ fbz,
                  const float* __restrict__ fWh, const float* __restrict__ fbh,
                  const float* __restrict__ ftw,
                  const float* __restrict__ Wih, const float* __restrict__ Whh,
                  const float* __restrict__ bih, const float* __restrict__ bhh,
                  const float* __restrict__ decW, const float* __restrict__ decb,
                  float* __restrict__ outs, float* __restrict__ hids)
{
    extern __shared__ float sm[];
    const int tid  = threadIdx.x;
    const int row0 = blockIdx.x * 32;

    const int w    = tid >> 5;
    const int lane = tid & 31;
    const int pg   = lane >> 3;          // pair-group 0..3 (pairs 4i+pg)
    const int cg   = lane & 7;           // col-group 0..7
    const int n0c  = w * 16 + cg * 2;    // consecutive cols (flow)
    const int n0s  = w * 8 + cg;         // split cols n0s, n0s+64 (GRU)

    const float* htb = sm + OFF_HT + pg * 264;
    const float* rhb = sm + OFF_RH + pg * 264;
    const float* xtb = sm + OFF_XT + pg * 88;

    // ---- one-time init ----
    for (int i = tid; i < 16 * 264; i += NTHR) sm[OFF_HT + i] = 0.0f;
    if (tid < 128) {
#pragma unroll
        for (int l = 0; l < 2; l++) {
            sm[OFF_FB + l * 512 +   0 + tid] = fbr[l * HH + tid];
            sm[OFF_FB + l * 512 + 128 + tid] = fbz[l * HH + tid];
            sm[OFF_FB + l * 512 + 256 + tid] = fbh[l * HH + tid];
            sm[OFF_FB + l * 512 + 384 + tid] = ftw[l * HH + tid];
        }
    }
    for (int i = tid; i < 384; i += NTHR) { sm[OFF_BIH + i] = bih[i]; sm[OFF_BHH + i] = bhh[i]; }
    if (tid < 32) sm[OFF_DB + tid] = decb[tid];
    for (int i = tid; i < 1024; i += NTHR) {       // dec [d][k] pad 132
        int r = i >> 5, c = i & 31;
        cpa16(sm + OFF_DEC + r * 132 + c * 4, decW + r * 128 + c * 4);
    }
    stage_matrix(0, sm, tid, fWr, fWz, fWh, Whh, Wih);
    CP_COMMIT();

#pragma unroll 1
    for (int ti = 0; ti < T_STEPS; ti++) {
        if (tid < 32) sm[OFF_TV + tid] = t[(size_t)(row0 + tid) * T_STEPS + ti];
        for (int i = tid; i < 32 * 40; i += NTHR) {
            const int m = i / 40, c = i - m * 40;
            const size_t row = row0 + m;
            const float v = (c < DS) ? s[(row * T_STEPS + ti) * DS + c]
                                     : a[(row * T_STEPS + ti) * DA + (c - DS)];
            sm[OFF_XT + (m >> 1) * 88 + 2 * c + (m & 1)] = v;
        }

        u64 zz[8], tvp[4];

        // =================== flow layers ===================
#pragma unroll 1
        for (int l = 0; l < 2; l++) {
            const int phb = l * 3;
            const float* bias = sm + OFF_FB + l * 512;

            // ---- pass r ----
            CP_WAIT0(); __syncthreads();
            stage_matrix(phb + 1, sm, tid, fWr, fWz, fWh, Whh, Wih); CP_COMMIT();
            {
                const float* sW = sm + (phb & 1) * SLOT;
#pragma unroll
                for (int i = 0; i < 4; i++) {
                    const int p = 4 * i + pg;
                    tvp[i] = pk2(sm[OFF_TV + 2 * p], sm[OFF_TV + 2 * p + 1]);
                }
                u64 acc[8];
#pragma unroll
                for (int q = 0; q < 8; q++) acc[q] = 0ULL;
                pass_flow(sW, htb, n0c, acc);
                const float2 wt = *(const float2*)&sW[128 * 128 + n0c];
                const u64 wta = pk2(wt.x, wt.x), wtb = pk2(wt.y, wt.y);
                const float br0 = bias[n0c], br1 = bias[n0c + 1];
#pragma unroll
                for (int i = 0; i < 4; i++) {
                    const int p = 4 * i + pg;
                    u64 a0 = fma2(tvp[i], wta, acc[2*i+0]);
                    u64 a1 = fma2(tvp[i], wtb, acc[2*i+1]);
                    float x, y;
                    up2(a0, x, y);
                    const u64 rr0 = pk2(0.8f * siga(x + br0), 0.8f * siga(y + br0));
                    up2(a1, x, y);
                    const u64 rr1 = pk2(0.8f * siga(x + br1), 0.8f * siga(y + br1));
                    const u64 h0 = *(const u64*)&sm[OFF_HT + p * 264 + 2 * n0c];
                    const u64 h1 = *(const u64*)&sm[OFF_HT + p * 264 + 2 * n0c + 2];
                    *(u64*)&sm[OFF_RH + p * 264 + 2 * n0c]     = mul2(rr0, h0);
                    *(u64*)&sm[OFF_RH + p * 264 + 2 * n0c + 2] = mul2(rr1, h1);
                }
            }

            // ---- pass z ----
            CP_WAIT0(); __syncthreads();
            stage_matrix(phb + 2, sm, tid, fWr, fWz, fWh, Whh, Wih); CP_COMMIT();
            {
                const float* sW = sm + ((phb + 1) & 1) * SLOT;
                u64 acc[8];
#pragma unroll
                for (int q = 0; q < 8; q++) acc[q] = 0ULL;
                pass_flow(sW, htb, n0c, acc);
                const float2 wt = *(const float2*)&sW[128 * 128 + n0c];
                const u64 wta = pk2(wt.x, wt.x), wtb = pk2(wt.y, wt.y);
                const float bz0 = bias[128 + n0c], bz1 = bias[128 + n0c + 1];
#pragma unroll
                for (int i = 0; i < 4; i++) {
                    u64 a0 = fma2(tvp[i], wta, acc[2*i+0]);
                    u64 a1 = fma2(tvp[i], wtb, acc[2*i+1]);
                    float x, y;
                    up2(a0, x, y); zz[2*i+0] = pk2(0.4f * siga(x + bz0), 0.4f * siga(y + bz0));
                    up2(a1, x, y); zz[2*i+1] = pk2(0.4f * siga(x + bz1), 0.4f * siga(y + bz1));
                }
            }

            // ---- pass u + combine ----
            CP_WAIT0(); __syncthreads();
            {
                stage_matrix(phb + 3, sm, tid, fWr, fWz, fWh, Whh, Wih); CP_COMMIT();
                const float* sW = sm + ((phb + 2) & 1) * SLOT;
                u64 acc[8];
#pragma unroll
                for (int q = 0; q < 8; q++) acc[q] = 0ULL;
                pass_flow(sW, rhb, n0c, acc);
                const float2 wt = *(const float2*)&sW[128 * 128 + n0c];
                const u64 wta = pk2(wt.x, wt.x), wtb = pk2(wt.y, wt.y);
                const float bh0 = bias[256 + n0c], bh1 = bias[256 + n0c + 1];
                const float tw0 = bias[384 + n0c], tw1 = bias[384 + n0c + 1];
                const u64 bh20 = pk2(bh0, bh0), bh21 = pk2(bh1, bh1);
                const u64 tw20 = pk2(tw0, tw0), tw21 = pk2(tw1, tw1);
#pragma unroll
                for (int i = 0; i < 4; i++) {
                    const int p = 4 * i + pg;
                    const u64 u0   = tanh2(add2(fma2(tvp[i], wta, acc[2*i+0]), bh20));
                    const u64 u1   = tanh2(add2(fma2(tvp[i], wtb, acc[2*i+1]), bh21));
                    const u64 phi0 = tanh2(mul2(tw20, tvp[i]));
                    const u64 phi1 = tanh2(mul2(tw21, tvp[i]));
                    const u64 h0 = *(const u64*)&sm[OFF_HT + p * 264 + 2 * n0c];
                    const u64 h1 = *(const u64*)&sm[OFF_HT + p * 264 + 2 * n0c + 2];
                    const u64 hn0 = fma2(mul2(phi0, zz[2*i+0]), sub2(u0, h0), h0);
                    const u64 hn1 = fma2(mul2(phi1, zz[2*i+1]), sub2(u1, h1), h1);
                    *(u64*)&sm[OFF_HT + p * 264 + 2 * n0c]     = hn0;
                    *(u64*)&sm[OFF_HT + p * 264 + 2 * n0c + 2] = hn1;
                    if (l == 1) {
                        float a0lo, a0hi, a1lo, a1hi;
                        up2(hn0, a0lo, a0hi); up2(hn1, a1lo, a1hi);
                        const size_t rg = row0 + 2 * p;
                        *(float2*)&hids[(rg * T_STEPS + ti) * (size_t)HH + n0c]       = make_float2(a0lo, a1lo);
                        *(float2*)&hids[((rg + 1) * T_STEPS + ti) * (size_t)HH + n0c] = make_float2(a0hi, a1hi);
                    }
                }
            }
        }

        // =================== GRU ===================
        u64 g_r[8], g_z[8], g_in[8], g_hn[8];
        {
            const float br0 = sm[OFF_BIH + n0s] + sm[OFF_BHH + n0s];
            const float br1 = sm[OFF_BIH + n0s + 64] + sm[OFF_BHH + n0s + 64];
            const float bz0 = sm[OFF_BIH + 128 + n0s] + sm[OFF_BHH + 128 + n0s];
            const float bz1 = sm[OFF_BIH + 128 + n0s + 64] + sm[OFF_BHH + 128 + n0s + 64];
            const float bi0 = sm[OFF_BIH + 256 + n0s],      bi1 = sm[OFF_BIH + 256 + n0s + 64];
            const float bn0 = sm[OFF_BHH + 256 + n0s],      bn1 = sm[OFF_BHH + 256 + n0s + 64];
#pragma unroll
            for (int i = 0; i < 4; i++) {
                g_r[2*i+0] = pk2(br0, br0); g_r[2*i+1] = pk2(br1, br1);
                g_z[2*i+0] = pk2(bz0, bz0); g_z[2*i+1] = pk2(bz1, bz1);
                g_in[2*i+0] = pk2(bi0, bi0); g_in[2*i+1] = pk2(bi1, bi1);
                g_hn[2*i+0] = pk2(bn0, bn0); g_hn[2*i+1] = pk2(bn1, bn1);
            }
        }
        // ghr (phase 6, slot 0)
        CP_WAIT0(); __syncthreads();
        stage_matrix(7, sm, tid, fWr, fWz, fWh, Whh, Wih); CP_COMMIT();
        pass_gh(sm + 0 * SLOT, htb, n0s, g_r);
        // ghz (phase 7, slot 1)
        CP_WAIT0(); __syncthreads();
        stage_matrix(8, sm, tid, fWr, fWz, fWh, Whh, Wih); CP_COMMIT();
        pass_gh(sm + 1 * SLOT, htb, n0s, g_z);
        // ghn (phase 8, slot 0)
        CP_WAIT0(); __syncthreads();
        stage_matrix(9, sm, tid, fWr, fWz, fWh, Whh, Wih); CP_COMMIT();
        pass_gh(sm + 0 * SLOT, htb, n0s, g_hn);
        // gi (phase 9, slot 1) + combine
        CP_WAIT0(); __syncthreads();
        stage_matrix(0, sm, tid, fWr, fWz, fWh, Whh, Wih); CP_COMMIT();   // next step Wr0
        {
            const float* sW = sm + 1 * SLOT;
            pass_gi(sW,            xtb, n0s, g_r);
            pass_gi(sW + 128 * 44, xtb, n0s, g_z);
            pass_gi(sW + 256 * 44, xtb, n0s, g_in);
#pragma unroll
            for (int i = 0; i < 4; i++) {
                const int p = 4 * i + pg;
#pragma unroll
                for (int c = 0; c < 2; c++) {
                    const int n = n0s + 64 * c;
                    float rx, ry, zx, zy;
                    up2(g_r[2*i+c], rx, ry); up2(g_z[2*i+c], zx, zy);
                    const u64 r2 = pk2(siga(rx), siga(ry));
                    const u64 z2 = pk2(siga(zx), siga(zy));
                    const u64 nn2 = tanh2(fma2(r2, g_hn[2*i+c], g_in[2*i+c]));
                    const u64 h2 = *(const u64*)&sm[OFF_HT + p * 264 + 2 * n];
                    const u64 hn2 = fma2(z2, sub2(h2, nn2), nn2);
                    *(u64*)&sm[OFF_HT + p * 264 + 2 * n] = hn2;
                }
            }
        }
        __syncthreads();   // h_new visible for decoder

        // =================== decoder ===================
        {
            const int d = tid & 31, grp = tid >> 5;
            const float db = sm[OFF_DB + d];
            u64 o0 = pk2(db, db), o1 = pk2(db, db);
            const float* xa0 = sm + OFF_HT + (2 * grp) * 264;
            const float* xa1 = xa0 + 264;
#pragma unroll 2
            for (int k = 0; k < 128; k += 4) {
                const float4 wv = *(const float4*)&sm[OFF_DEC + d * 132 + k];
                const u64 wa = pk2(wv.x, wv.x), wb = pk2(wv.y, wv.y);
                const u64 wc = pk2(wv.z, wv.z), wd = pk2(wv.w, wv.w);
                u64 x0, x1, x2, x3;
                LDX2(x0, x1, xa0 + k * 2);
                LDX2(x2, x3, xa0 + k * 2 + 4);
                o0 = fma2(x0, wa, o0); o0 = fma2(x1, wb, o0);
                o0 = fma2(x2, wc, o0); o0 = fma2(x3, wd, o0);
                LDX2(x0, x1, xa1 + k * 2);
                LDX2(x2, x3, xa1 + k * 2 + 4);
                o1 = fma2(x0, wa, o1); o1 = fma2(x1, wb, o1);
                o1 = fma2(x2, wc, o1); o1 = fma2(x3, wd, o1);
            }
            float v0, v1, v2, v3;
            up2(o0, v0, v1); up2(o1, v2, v3);
            const size_t r0g = row0 + 4 * grp;
            outs[((r0g + 0) * T_STEPS + ti) * (size_t)DS + d] = v0;
            outs[((r0g + 1) * T_STEPS + ti) * (size_t)DS + d] = v1;
            outs[((r0g + 2) * T_STEPS + ti) * (size_t)DS + d] = v2;
            outs[((r0g + 3) * T_STEPS + ti) * (size_t)DS + d] = v3;
        }
    }
}

extern "C" void kernel_launch(void* const* d_in, const int* in_sizes, int n_in,
                              void* d_out, int out_size)
{
    const float* s    = (const float*)d_in[0];
    const float* a    = (const float*)d_in[1];
    const float* t    = (const float*)d_in[2];
    const float* fWr  = (const float*)d_in[3];
    const float* fbr  = (const float*)d_in[4];
    const float* fWz  = (const float*)d_in[5];
    const float* fbz  = (const float*)d_in[6];
    const float* fWh  = (const float*)d_in[7];
    const float* fbh  = (const float*)d_in[8];
    const float* ftw  = (const float*)d_in[9];
    const float* Wih  = (const float*)d_in[10];
    const float* Whh  = (const float*)d_in[11];
    const float* bih  = (const float*)d_in[12];
    const float* bhh  = (const float*)d_in[13];
    const float* decW = (const float*)d_in[14];
    const float* decb = (const float*)d_in[15];

    float* outs = (float*)d_out;
    float* hids = outs + (size_t)4096 * T_STEPS * DS;

    const int SMEM = SMEM_FL * 4;
    cudaFuncSetAttribute(odernn_persistent, cudaFuncAttributeMaxDynamicSharedMemorySize, SMEM);
    odernn_persistent<<<128, NTHR, SMEM>>>(s, a, t, fWr, fbr, fWz, fbz, fWh, fbh, ftw,
                                           Wih, Whh, bih, bhh, decW, decb, outs, hids);
}